// round 14
// baseline (speedup 1.0000x reference)
#include <cuda_runtime.h>

#define R_N 1000
#define C_N 81
#define NC  80          // foreground classes == grid size
#define NEGV (-1e9f)
#define SCORE_T 0.05f
#define IOU_T 0.5f
#define TOPK 100
#define GRID NC
#define BLOCK 512
#define SELCAP 2048
#define CANDMAX 512

// ---------------- device scratch (no allocations allowed) ----------------
__device__ int g_cnt[NC];                          // per-class pre-NMS counts
__device__ unsigned long long g_clist[NC * R_N];   // per-class key lists
__device__ unsigned long long g_pool[NC * R_N];    // post-NMS survivor keys
__device__ float4 g_pbox[NC * R_N];                // survivor boxes by flat idx
__device__ int g_count;
__device__ int g_aflag[NC];                        // phase-A arrival flags
__device__ int g_bflag[NC];                        // phase-B arrival flags
__device__ int g_lock;                             // phase-C uniqueness lock

// ---------------- helpers ----------------
__device__ __forceinline__ unsigned int ord32(float f) {
    unsigned int u = __float_as_uint(f);
    return (u & 0x80000000u) ? ~u : (u | 0x80000000u);
}
__device__ __forceinline__ float unord32(unsigned int u) {
    unsigned int b = (u & 0x80000000u) ? (u ^ 0x80000000u) : ~u;
    return __uint_as_float(b);
}
__device__ __forceinline__ float load_dim(const void* p) {
    int iv = *(const int*)p;
    if (iv > 0 && iv < 1000000) return (float)iv;   // passed as int
    return *(const float*)p;                         // passed as float
}
__device__ __forceinline__ void push_key(int c, int row, float prob,
                                         const float4* reg4, const float4* props4) {
    // c in 1..80 (pre-NMS per-class list)
    if (prob > SCORE_T) {
        int slot = atomicAdd(&g_cnt[c - 1], 1);
        g_clist[(c - 1) * R_N + slot] =
            ((unsigned long long)ord32(prob) << 32) | (unsigned int)(~row);
        // warm L2 for phase-B decode (fire-and-forget)
        asm volatile("prefetch.global.L2 [%0];" :: "l"(&reg4[(size_t)row * C_N + c]));
        asm volatile("prefetch.global.L2 [%0];" :: "l"(&props4[row]));
    }
}
// monotone 11-bit score bin (key bits 51..61; bits 62..63 constant for 0<score<2)
__device__ __forceinline__ int kbin(unsigned long long k) {
    return (int)(k >> 51) & (SELCAP - 1);
}

// decode + clip one box (class c in [1,80], row r) — exact reference math
__device__ __forceinline__ float4 decode_box(const float4* __restrict__ props4,
                                             const float4* __restrict__ reg4,
                                             int r, int c, float W, float H) {
    const float CLIPV = 4.135166556742356f;   // log(1000/16)
    float4 p = props4[r];
    float bw = p.z - p.x + 1.f, bh = p.w - p.y + 1.f;
    float cx = p.x + 0.5f * bw,  cy = p.y + 0.5f * bh;
    float4 rr = reg4[(size_t)r * C_N + c];
    float dx = rr.x / 10.0f;
    float dy = rr.y / 10.0f;
    float dw = fminf(rr.z / 5.0f, CLIPV);
    float dh = fminf(rr.w / 5.0f, CLIPV);
    float pcx = dx * bw + cx;
    float pcy = dy * bh + cy;
    float pw2 = expf(dw) * bw;
    float ph2 = expf(dh) * bh;
    float x1 = fminf(fmaxf(pcx - 0.5f * pw2, 0.f), W - 1.f);
    float y1 = fminf(fmaxf(pcy - 0.5f * ph2, 0.f), H - 1.f);
    float x2 = fminf(fmaxf(pcx + 0.5f * pw2 - 1.f, 0.f), W - 1.f);
    float y2 = fminf(fmaxf(pcy + 0.5f * ph2 - 1.f, 0.f), H - 1.f);
    return make_float4(x1, y1, x2, y2);
}

// shared scratch (phases temporally disjoint)
union Scratch {
    struct {                                  // phase B
        unsigned long long skey[1024];
        float sx1[1024], sy1[1024], sx2[1024], sy2[1024], sar[1024];
        unsigned char srem[1024];
        unsigned long long smask[64];
        unsigned long long keep;
    } b;
    struct {                                  // phase C
        unsigned long long cand[SELCAP];
        int hist[SELCAP];
        unsigned long long sel[CANDMAX];
    } c;
};

__device__ void bitonic_desc(unsigned long long* a, int n) {
    for (unsigned int k = 2; k <= (unsigned int)n; k <<= 1) {
        for (unsigned int j = k >> 1; j > 0; j >>= 1) {
            for (unsigned int i = threadIdx.x; i < (unsigned int)n; i += BLOCK) {
                unsigned int l = i ^ j;
                if (l > i) {
                    unsigned long long x = a[i], y = a[l];
                    bool up = ((i & k) == 0);
                    if (up ? (x < y) : (x > y)) { a[i] = y; a[l] = x; }
                }
            }
            __syncthreads();
        }
    }
}

// ---------------- the single fused kernel ----------------
__global__ void __launch_bounds__(BLOCK) k_fused(
        const float* __restrict__ logits,
        const float* __restrict__ reg,
        const float* __restrict__ props,
        const void* pw, const void* ph,
        float* __restrict__ out) {

    __shared__ Scratch u;
    __shared__ int wtot[16];
    __shared__ int s_cnt, s_thr, s_tot, s_doC, s_d, s_cum, s_bin;

    int tid = threadIdx.x;
    int wid = tid >> 5;
    int lane = tid & 31;
    const float4* props4 = (const float4*)props;
    const float4* reg4 = (const float4*)reg;

    // ---------- Phase A: softmax stats + score filter + per-class push ----------
    {
        int row = blockIdx.x * (BLOCK / 32) + wid;   // one warp per row, contiguous
        if (row < R_N) {
            const float* lg = logits + (size_t)row * C_N;
            float a = (lane      < C_N) ? lg[lane]      : -INFINITY;
            float b = (lane + 32 < C_N) ? lg[lane + 32] : -INFINITY;
            float d = (lane + 64 < C_N) ? lg[lane + 64] : -INFINITY;
            float m = fmaxf(a, fmaxf(b, d));
            for (int o = 16; o; o >>= 1) m = fmaxf(m, __shfl_xor_sync(0xffffffffu, m, o));
            float ea = (lane      < C_N) ? expf(a - m) : 0.f;
            float eb = (lane + 32 < C_N) ? expf(b - m) : 0.f;
            float ed = (lane + 64 < C_N) ? expf(d - m) : 0.f;
            float s = ea + eb + ed;
            for (int o = 16; o; o >>= 1) s += __shfl_xor_sync(0xffffffffu, s, o);
            float inv = 1.f / s;
            if (lane >= 1)  push_key(lane,      row, ea * inv, reg4, props4);   // c = 1..31
            push_key(lane + 32, row, eb * inv, reg4, props4);                   // c = 32..63
            if (lane <= 16) push_key(lane + 64, row, ed * inv, reg4, props4);   // c = 64..80
        }
    }
    __syncthreads();
    __threadfence();
    // ---- A-barrier: flag store (no same-address atomics) + warp-0 ballot poll ----
    if (tid == 0) {
        *(volatile int*)&g_aflag[blockIdx.x] = 1;
        __threadfence();
    }
    if (wid == 0) {
        int i1 = lane + 32, i2 = lane + 64;
        for (;;) {
            int f0 = *(volatile int*)&g_aflag[lane];
            int f1 = *(volatile int*)&g_aflag[i1];
            int f2 = (i2 < NC) ? *(volatile int*)&g_aflag[i2] : 1;
            if (__all_sync(0xffffffffu, f0 && f1 && f2)) break;
        }
    }
    __syncthreads();
    __threadfence();

    // W/H needed only post-barrier — keep these loads off the phase-A critical path
    float W = load_dim(pw), H = load_dim(ph);

    // ---------- Phase B: per-class NMS on pre-filtered list ----------
    int c0 = blockIdx.x;
    int c = c0 + 1;
    int M = *(volatile int*)&g_cnt[c0];

    if (M > 0 && M <= 64) {
        if (tid < M) u.b.skey[tid] = __ldcg(&g_clist[c0 * R_N + tid]);
        __syncthreads();
        unsigned long long mykey = 0ULL;
        float4 b;
        float A = 0.f;
        int rank = 0;
        if (tid < M) {
            mykey = u.b.skey[tid];
            for (int j = 0; j < M; j++) rank += (u.b.skey[j] > mykey);
            int r = (int)(~(unsigned int)mykey);
            b = decode_box(props4, reg4, r, c, W, H);
            A = (b.z - b.x + 1.f) * (b.w - b.y + 1.f);
            u.b.sx1[rank] = b.x; u.b.sy1[rank] = b.y;
            u.b.sx2[rank] = b.z; u.b.sy2[rank] = b.w;
            u.b.sar[rank] = A;
        }
        __syncthreads();
        if (tid < M) {
            unsigned long long msk = 0ULL;
            for (int j = rank + 1; j < M; j++) {
                float ix1 = fmaxf(b.x, u.b.sx1[j]), iy1 = fmaxf(b.y, u.b.sy1[j]);
                float ix2 = fminf(b.z, u.b.sx2[j]), iy2 = fminf(b.w, u.b.sy2[j]);
                float iw = fmaxf(ix2 - ix1 + 1.f, 0.f);
                float ih = fmaxf(iy2 - iy1 + 1.f, 0.f);
                float inter = iw * ih;
                float iou = inter / (A + u.b.sar[j] - inter);
                if (iou > IOU_T) msk |= (1ULL << j);
            }
            u.b.smask[rank] = msk;
        }
        __syncthreads();
        if (tid == 0) {
            unsigned long long removed = 0ULL, keep = 0ULL;
            for (int i = 0; i < M; i++)
                if (!((removed >> i) & 1ULL)) { keep |= (1ULL << i); removed |= u.b.smask[i]; }
            u.b.keep = keep;
        }
        __syncthreads();
        if (tid < M && ((u.b.keep >> rank) & 1ULL)) {
            unsigned int r = ~(unsigned int)mykey;
            unsigned int flat = (unsigned int)(c0 * R_N) + r;
            int p = atomicAdd(&g_count, 1);
            g_pool[p] = (mykey & 0xffffffff00000000ULL) | (unsigned int)(~flat);
            g_pbox[flat] = b;
        }
    } else if (M > 64) {
        // fallback: sorted serial greedy (rare)
        int Mf = min(M, 1024);
        for (int i = tid; i < Mf; i += BLOCK) u.b.skey[i] = __ldcg(&g_clist[c0 * R_N + i]);
        int n = 1; while (n < Mf) n <<= 1;
        for (int i = Mf + tid; i < n; i += BLOCK) u.b.skey[i] = 0ULL;
        __syncthreads();
        bitonic_desc(u.b.skey, n);
        for (int i = tid; i < Mf; i += BLOCK) {
            int r = (int)(~(unsigned int)u.b.skey[i]);
            float4 b = decode_box(props4, reg4, r, c, W, H);
            u.b.sx1[i] = b.x; u.b.sy1[i] = b.y; u.b.sx2[i] = b.z; u.b.sy2[i] = b.w;
            u.b.sar[i] = (b.z - b.x + 1.f) * (b.w - b.y + 1.f);
            u.b.srem[i] = 0;
        }
        __syncthreads();
        for (int i = 0; i < Mf; i++) {
            if (!u.b.srem[i]) {
                float X1 = u.b.sx1[i], Y1 = u.b.sy1[i], X2 = u.b.sx2[i], Y2 = u.b.sy2[i];
                float A = u.b.sar[i];
                for (int j = i + 1 + tid; j < Mf; j += BLOCK) {
                    if (!u.b.srem[j]) {
                        float ix1 = fmaxf(X1, u.b.sx1[j]), iy1 = fmaxf(Y1, u.b.sy1[j]);
                        float ix2 = fminf(X2, u.b.sx2[j]), iy2 = fminf(Y2, u.b.sy2[j]);
                        float iw = fmaxf(ix2 - ix1 + 1.f, 0.f);
                        float ih = fmaxf(iy2 - iy1 + 1.f, 0.f);
                        float inter = iw * ih;
                        if (inter / (A + u.b.sar[j] - inter) > IOU_T) u.b.srem[j] = 1;
                    }
                }
            }
            __syncthreads();
        }
        for (int i = tid; i < Mf; i += BLOCK) {
            if (!u.b.srem[i]) {
                unsigned long long kk = u.b.skey[i];
                unsigned int r = ~(unsigned int)kk;
                unsigned int flat = (unsigned int)(c0 * R_N) + r;
                int p = atomicAdd(&g_count, 1);
                g_pool[p] = (kk & 0xffffffff00000000ULL) | (unsigned int)(~flat);
                g_pbox[flat] = make_float4(u.b.sx1[i], u.b.sy1[i], u.b.sx2[i], u.b.sy2[i]);
            }
        }
    }

    // ---- B-handoff: flag store + ONE-SHOT all-check; lock for uniqueness ----
    __syncthreads();
    __threadfence();
    if (tid == 0) {
        *(volatile int*)&g_bflag[blockIdx.x] = 1;
        __threadfence();
    }
    __syncthreads();
    int myf = (tid < NC) ? *(volatile int*)&g_bflag[tid] : 1;
    int allset = __syncthreads_and(myf != 0);
    if (!allset) return;                      // someone later will see all-set
    if (tid == 0) s_doC = (atomicExch(&g_lock, 1) == 0);
    __syncthreads();
    if (!s_doC) return;                       // another candidate won the lock
    __threadfence();

    // ---------- Phase C: shared-hist threshold + rank placement ----------
    int K = *(volatile int*)&g_count;
    int count = 0;

    if (K <= TOPK) {
        for (int i = tid; i < K; i += BLOCK) u.c.sel[i] = __ldcg(&g_pool[i]);
        count = K;
        __syncthreads();
    } else {
        bool smallK = (K <= SELCAP);
        if (smallK) for (int i = tid; i < K; i += BLOCK) u.c.cand[i] = __ldcg(&g_pool[i]);
        #pragma unroll
        for (int q = 0; q < SELCAP / BLOCK; q++) u.c.hist[tid + q * BLOCK] = 0;
        __syncthreads();
        for (int i = tid; i < K; i += BLOCK) {
            unsigned long long k = smallK ? u.c.cand[i] : __ldcg(&g_pool[i]);
            atomicAdd(&u.c.hist[kbin(k)], 1);
        }
        __syncthreads();
        // 3-barrier warp-shfl suffix scan over 2048 bins (4 bins/thread)
        int base = tid * 4;
        int h0 = u.c.hist[base], h1 = u.c.hist[base + 1];
        int h2 = u.c.hist[base + 2], h3 = u.c.hist[base + 3];
        int cs = h0 + h1 + h2 + h3;
        int v = cs;
        #pragma unroll
        for (int off = 1; off < 32; off <<= 1) {
            int nv = __shfl_down_sync(0xffffffffu, v, off);
            if (lane + off < 32) v += nv;
        }
        if (lane == 0) wtot[wid] = v;
        __syncthreads();
        if (wid == 0) {
            int w = (lane < 16) ? wtot[lane] : 0;
            #pragma unroll
            for (int off = 1; off < 16; off <<= 1) {
                int nw = __shfl_down_sync(0xffffffffu, w, off);
                if (lane + off < 16) w += nw;
            }
            if (lane < 16) wtot[lane] = w;   // suffix over warps lane..15
        }
        __syncthreads();
        int S = v + ((wid < 15) ? wtot[wid + 1] : 0);   // keys with bin >= base
        int cum = S - cs;                                // keys with bin > base+3
        int hh[4] = {h0, h1, h2, h3};
        #pragma unroll
        for (int b = 3; b >= 0; b--) {
            int h = hh[b];
            if (cum < TOPK && cum + h >= TOPK) { s_thr = base + b; s_tot = cum + h; }
            cum += h;
        }
        __syncthreads();
        int thr = s_thr;
        if (s_tot <= CANDMAX) {
            if (tid == 0) s_cnt = 0;
            __syncthreads();
            for (int i = tid; i < K; i += BLOCK) {
                unsigned long long k = smallK ? u.c.cand[i] : __ldcg(&g_pool[i]);
                if (kbin(k) >= thr) u.c.sel[atomicAdd(&s_cnt, 1)] = k;
            }
            __syncthreads();
            count = s_cnt;
        } else {
            // pathological ties: adaptive 64-bit radix descent on g_pool
            unsigned long long prefix = 0;
            int shift = 56, needed = TOPK;
            for (;;) {
                for (int i = tid; i < 256; i += BLOCK) u.c.hist[i] = 0;
                __syncthreads();
                for (int i = tid; i < K; i += BLOCK) {
                    unsigned long long k = __ldcg(&g_pool[i]);
                    bool act = (shift == 56) || ((k >> (shift + 8)) == prefix);
                    if (act) atomicAdd(&u.c.hist[(int)((k >> shift) & 255)], 1);
                }
                __syncthreads();
                if (tid == 0) {
                    int cum2 = 0, d;
                    for (d = 255; d > 0; d--) {
                        int h = u.c.hist[d];
                        if (cum2 + h >= needed) break;
                        cum2 += h;
                    }
                    s_d = d; s_cum = cum2; s_bin = u.c.hist[d];
                }
                __syncthreads();
                needed -= s_cum;
                prefix = (prefix << 8) | (unsigned int)s_d;
                int binCount = s_bin;
                shift -= 8;
                if ((TOPK - needed) + binCount <= CANDMAX || shift < 0) break;
                __syncthreads();
            }
            if (tid == 0) s_cnt = 0;
            __syncthreads();
            int sh = shift + 8;
            for (int i = tid; i < K; i += BLOCK) {
                unsigned long long k = __ldcg(&g_pool[i]);
                if ((k >> sh) >= prefix) {
                    int p = atomicAdd(&s_cnt, 1);
                    if (p < CANDMAX) u.c.sel[p] = k;
                }
            }
            __syncthreads();
            count = min(s_cnt, CANDMAX);
        }
    }

    // rank placement (keys unique -> exact ranks)
    for (int i = tid; i < count; i += BLOCK) {
        unsigned long long kk = u.c.sel[i];
        int rank = 0;
        for (int j = 0; j < count; j++) rank += (u.c.sel[j] > kk);
        if (rank < TOPK) {
            unsigned int flat = ~(unsigned int)(kk & 0xffffffffu);
            float score = unord32((unsigned int)(kk >> 32));
            int cc = flat / R_N;
            float4 b = g_pbox[flat];
            out[rank] = score;
            out[TOPK + 4 * rank + 0] = b.x;
            out[TOPK + 4 * rank + 1] = b.y;
            out[TOPK + 4 * rank + 2] = b.z;
            out[TOPK + 4 * rank + 3] = b.w;
            out[5 * TOPK + rank] = (float)(cc + 1);
        }
    }
    __syncthreads();
    if (count < TOPK && tid == 0) {
        // K < 100: fill remaining slots NEG-score, ascending unused flat idx
        int p = count;
        for (int f = 0; p < TOPK; f++) {
            bool used = false;
            for (int q = 0; q < count; q++) {
                unsigned int fl = ~(unsigned int)(u.c.sel[q] & 0xffffffffu);
                if ((int)fl == f) { used = true; break; }
            }
            if (!used) {
                int cc = f / R_N;
                int r = f - cc * R_N;
                float4 b = decode_box(props4, reg4, r, cc + 1, W, H);
                out[p] = NEGV;
                out[TOPK + 4 * p + 0] = b.x;
                out[TOPK + 4 * p + 1] = b.y;
                out[TOPK + 4 * p + 2] = b.z;
                out[TOPK + 4 * p + 3] = b.w;
                out[5 * TOPK + p] = (float)(cc + 1);
                p++;
            }
        }
    }

    // reset for next graph replay (only this block alive)
    __syncthreads();
    if (tid < NC) { g_cnt[tid] = 0; g_aflag[tid] = 0; g_bflag[tid] = 0; }
    if (tid == 0) { g_count = 0; g_lock = 0; }
    __threadfence();
}

// ---------------- launch ----------------
extern "C" void kernel_launch(void* const* d_in, const int* in_sizes, int n_in,
                              void* d_out, int out_size) {
    const float *logits = nullptr, *reg = nullptr, *props = nullptr;
    const void *pw = nullptr, *ph = nullptr;
    for (int i = 0; i < n_in; i++) {
        int s = in_sizes[i];
        if (s == R_N * C_N)            logits = (const float*)d_in[i];
        else if (s == R_N * C_N * 4)   reg    = (const float*)d_in[i];
        else if (s == R_N * 4)         props  = (const float*)d_in[i];
        else if (s == 1) { if (!pw) pw = d_in[i]; else ph = d_in[i]; }
    }
    k_fused<<<GRID, BLOCK>>>(logits, reg, props, pw, ph, (float*)d_out);
}

// round 17
// speedup vs baseline: 1.1592x; 1.1592x over previous
#include <cuda_runtime.h>

#define R_N 1000
#define C_N 81
#define NC  80          // foreground classes == grid size
#define NEGV (-1e9f)
#define SCORE_T 0.05f
#define IOU_T 0.5f
#define TOPK 100
#define GRID NC
#define BLOCK 512
#define SELCAP 2048
#define CANDMAX 512

// ---------------- device scratch (no allocations allowed) ----------------
__device__ int g_cnt[NC];                          // per-class pre-NMS counts
__device__ unsigned long long g_clist[NC * R_N];   // per-class key lists
__device__ unsigned long long g_pool[NC * R_N];    // post-NMS survivor keys
__device__ float4 g_pbox[NC * R_N];                // survivor boxes by flat idx
__device__ int g_count;
__device__ int g_c1, g_c2;                         // barrier / ticket counters

// ---------------- helpers ----------------
__device__ __forceinline__ unsigned int ord32(float f) {
    unsigned int u = __float_as_uint(f);
    return (u & 0x80000000u) ? ~u : (u | 0x80000000u);
}
__device__ __forceinline__ float unord32(unsigned int u) {
    unsigned int b = (u & 0x80000000u) ? (u ^ 0x80000000u) : ~u;
    return __uint_as_float(b);
}
__device__ __forceinline__ float load_dim(const void* p) {
    int iv = *(const int*)p;
    if (iv > 0 && iv < 1000000) return (float)iv;   // passed as int
    return *(const float*)p;                         // passed as float
}
__device__ __forceinline__ void push_key(int c, int row, float prob,
                                         const float4* reg4, const float4* props4) {
    // c in 1..80 (pre-NMS per-class list)
    if (prob > SCORE_T) {
        int slot = atomicAdd(&g_cnt[c - 1], 1);
        g_clist[(c - 1) * R_N + slot] =
            ((unsigned long long)ord32(prob) << 32) | (unsigned int)(~row);
        // warm L2 for phase-B decode (fire-and-forget)
        asm volatile("prefetch.global.L2 [%0];" :: "l"(&reg4[(size_t)row * C_N + c]));
        asm volatile("prefetch.global.L2 [%0];" :: "l"(&props4[row]));
    }
}
// monotone 11-bit score bin (key bits 51..61; bits 62..63 constant for 0<score<2)
__device__ __forceinline__ int kbin(unsigned long long k) {
    return (int)(k >> 51) & (SELCAP - 1);
}

// decode + clip one box (class c in [1,80], row r) — exact reference math
__device__ __forceinline__ float4 decode_box(const float4* __restrict__ props4,
                                             const float4* __restrict__ reg4,
                                             int r, int c, float W, float H) {
    const float CLIPV = 4.135166556742356f;   // log(1000/16)
    float4 p = props4[r];
    float bw = p.z - p.x + 1.f, bh = p.w - p.y + 1.f;
    float cx = p.x + 0.5f * bw,  cy = p.y + 0.5f * bh;
    float4 rr = reg4[(size_t)r * C_N + c];
    float dx = rr.x / 10.0f;
    float dy = rr.y / 10.0f;
    float dw = fminf(rr.z / 5.0f, CLIPV);
    float dh = fminf(rr.w / 5.0f, CLIPV);
    float pcx = dx * bw + cx;
    float pcy = dy * bh + cy;
    float pw2 = expf(dw) * bw;
    float ph2 = expf(dh) * bh;
    float x1 = fminf(fmaxf(pcx - 0.5f * pw2, 0.f), W - 1.f);
    float y1 = fminf(fmaxf(pcy - 0.5f * ph2, 0.f), H - 1.f);
    float x2 = fminf(fmaxf(pcx + 0.5f * pw2 - 1.f, 0.f), W - 1.f);
    float y2 = fminf(fmaxf(pcy + 0.5f * ph2 - 1.f, 0.f), H - 1.f);
    return make_float4(x1, y1, x2, y2);
}

// shared scratch (phases temporally disjoint)
union Scratch {
    struct {                                  // phase B
        unsigned long long skey[1024];
        float sx1[1024], sy1[1024], sx2[1024], sy2[1024], sar[1024];
        unsigned char srem[1024];
        unsigned long long smask[64];
        unsigned long long keep;
    } b;
    struct {                                  // phase C
        unsigned long long cand[SELCAP];
        int hist[SELCAP];
        unsigned long long sel[CANDMAX];
    } c;
};

__device__ void bitonic_desc(unsigned long long* a, int n) {
    for (unsigned int k = 2; k <= (unsigned int)n; k <<= 1) {
        for (unsigned int j = k >> 1; j > 0; j >>= 1) {
            for (unsigned int i = threadIdx.x; i < (unsigned int)n; i += BLOCK) {
                unsigned int l = i ^ j;
                if (l > i) {
                    unsigned long long x = a[i], y = a[l];
                    bool up = ((i & k) == 0);
                    if (up ? (x < y) : (x > y)) { a[i] = y; a[l] = x; }
                }
            }
            __syncthreads();
        }
    }
}

// ---------------- the single fused kernel ----------------
__global__ void __launch_bounds__(BLOCK) k_fused(
        const float* __restrict__ logits,
        const float* __restrict__ reg,
        const float* __restrict__ props,
        const void* pw, const void* ph,
        float* __restrict__ out) {

    __shared__ Scratch u;
    __shared__ int wtot[16];
    __shared__ int s_cnt, s_thr, s_tot, s_doC, s_d, s_cum, s_bin;

    int tid = threadIdx.x;
    int wid = tid >> 5;
    int lane = tid & 31;
    const float4* props4 = (const float4*)props;
    const float4* reg4 = (const float4*)reg;

    // ---------- Phase A: softmax stats + score filter + per-class push ----------
    {
        int row = blockIdx.x * (BLOCK / 32) + wid;   // one warp per row, contiguous
        if (row < R_N) {
            const float* lg = logits + (size_t)row * C_N;
            float a = (lane      < C_N) ? lg[lane]      : -INFINITY;
            float b = (lane + 32 < C_N) ? lg[lane + 32] : -INFINITY;
            float d = (lane + 64 < C_N) ? lg[lane + 64] : -INFINITY;
            float m = fmaxf(a, fmaxf(b, d));
            for (int o = 16; o; o >>= 1) m = fmaxf(m, __shfl_xor_sync(0xffffffffu, m, o));
            float ea = (lane      < C_N) ? expf(a - m) : 0.f;
            float eb = (lane + 32 < C_N) ? expf(b - m) : 0.f;
            float ed = (lane + 64 < C_N) ? expf(d - m) : 0.f;
            float s = ea + eb + ed;
            for (int o = 16; o; o >>= 1) s += __shfl_xor_sync(0xffffffffu, s, o);
            float inv = 1.f / s;
            if (lane >= 1)  push_key(lane,      row, ea * inv, reg4, props4);   // c = 1..31
            push_key(lane + 32, row, eb * inv, reg4, props4);                   // c = 32..63
            if (lane <= 16) push_key(lane + 64, row, ed * inv, reg4, props4);   // c = 64..80
        }
    }
    __syncthreads();
    __threadfence();
    if (tid == 0) {
        atomicAdd(&g_c1, 1);
        while (*(volatile int*)&g_c1 < GRID) __nanosleep(32);   // all 80 blocks resident
    }
    __syncthreads();
    __threadfence();

    // W/H needed only post-barrier — keep these loads off the phase-A critical path
    float W = load_dim(pw), H = load_dim(ph);

    // ---------- Phase B: per-class NMS on pre-filtered list ----------
    int c0 = blockIdx.x;
    int c = c0 + 1;
    int M = *(volatile int*)&g_cnt[c0];

    if (M > 0 && M <= 64) {
        if (tid < M) u.b.skey[tid] = __ldcg(&g_clist[c0 * R_N + tid]);
        __syncthreads();
        unsigned long long mykey = 0ULL;
        float4 b;
        float A = 0.f;
        int rank = 0;
        if (tid < M) {
            mykey = u.b.skey[tid];
            for (int j = 0; j < M; j++) rank += (u.b.skey[j] > mykey);
            int r = (int)(~(unsigned int)mykey);
            b = decode_box(props4, reg4, r, c, W, H);
            A = (b.z - b.x + 1.f) * (b.w - b.y + 1.f);
            u.b.sx1[rank] = b.x; u.b.sy1[rank] = b.y;
            u.b.sx2[rank] = b.z; u.b.sy2[rank] = b.w;
            u.b.sar[rank] = A;
        }
        __syncthreads();
        if (tid < M) {
            // suppressor mask: higher-ranked boxes j < rank with IoU > thr
            unsigned long long msk = 0ULL;
            for (int j = 0; j < rank; j++) {
                float ix1 = fmaxf(b.x, u.b.sx1[j]), iy1 = fmaxf(b.y, u.b.sy1[j]);
                float ix2 = fminf(b.z, u.b.sx2[j]), iy2 = fminf(b.w, u.b.sy2[j]);
                float iw = fmaxf(ix2 - ix1 + 1.f, 0.f);
                float ih = fmaxf(iy2 - iy1 + 1.f, 0.f);
                float inter = iw * ih;
                float iou = inter / (A + u.b.sar[j] - inter);
                if (iou > IOU_T) msk |= (1ULL << j);
            }
            u.b.smask[rank] = msk;
        }
        __syncthreads();
        if (wid == 0) {
            // warp-ballot fixpoint == greedy (suppressor-mask orientation; R3-validated)
            unsigned long long m0 = (lane < M)      ? u.b.smask[lane]      : ~0ULL;
            unsigned long long m1 = (lane + 32 < M) ? u.b.smask[lane + 32] : ~0ULL;
            unsigned long long full = (M == 64) ? ~0ULL : ((1ULL << M) - 1ULL);
            unsigned long long keep = full;
            for (int it = 0; it <= M; it++) {
                bool b0 = (lane < M)      && ((m0 & keep) == 0ULL);
                bool b1 = (lane + 32 < M) && ((m1 & keep) == 0ULL);
                unsigned int lo = __ballot_sync(0xffffffffu, b0);
                unsigned int hi = __ballot_sync(0xffffffffu, b1);
                unsigned long long nk = (((unsigned long long)hi << 32) | lo) & full;
                if (nk == keep) break;
                keep = nk;
            }
            if (lane == 0) u.b.keep = keep;
        }
        __syncthreads();
        if (tid < M && ((u.b.keep >> rank) & 1ULL)) {
            unsigned int r = ~(unsigned int)mykey;
            unsigned int flat = (unsigned int)(c0 * R_N) + r;
            int p = atomicAdd(&g_count, 1);
            g_pool[p] = (mykey & 0xffffffff00000000ULL) | (unsigned int)(~flat);
            g_pbox[flat] = b;
        }
    } else if (M > 64) {
        // fallback: sorted serial greedy (rare)
        int Mf = min(M, 1024);
        for (int i = tid; i < Mf; i += BLOCK) u.b.skey[i] = __ldcg(&g_clist[c0 * R_N + i]);
        int n = 1; while (n < Mf) n <<= 1;
        for (int i = Mf + tid; i < n; i += BLOCK) u.b.skey[i] = 0ULL;
        __syncthreads();
        bitonic_desc(u.b.skey, n);
        for (int i = tid; i < Mf; i += BLOCK) {
            int r = (int)(~(unsigned int)u.b.skey[i]);
            float4 b = decode_box(props4, reg4, r, c, W, H);
            u.b.sx1[i] = b.x; u.b.sy1[i] = b.y; u.b.sx2[i] = b.z; u.b.sy2[i] = b.w;
            u.b.sar[i] = (b.z - b.x + 1.f) * (b.w - b.y + 1.f);
            u.b.srem[i] = 0;
        }
        __syncthreads();
        for (int i = 0; i < Mf; i++) {
            if (!u.b.srem[i]) {
                float X1 = u.b.sx1[i], Y1 = u.b.sy1[i], X2 = u.b.sx2[i], Y2 = u.b.sy2[i];
                float A = u.b.sar[i];
                for (int j = i + 1 + tid; j < Mf; j += BLOCK) {
                    if (!u.b.srem[j]) {
                        float ix1 = fmaxf(X1, u.b.sx1[j]), iy1 = fmaxf(Y1, u.b.sy1[j]);
                        float ix2 = fminf(X2, u.b.sx2[j]), iy2 = fminf(Y2, u.b.sy2[j]);
                        float iw = fmaxf(ix2 - ix1 + 1.f, 0.f);
                        float ih = fmaxf(iy2 - iy1 + 1.f, 0.f);
                        float inter = iw * ih;
                        if (inter / (A + u.b.sar[j] - inter) > IOU_T) u.b.srem[j] = 1;
                    }
                }
            }
            __syncthreads();
        }
        for (int i = tid; i < Mf; i += BLOCK) {
            if (!u.b.srem[i]) {
                unsigned long long kk = u.b.skey[i];
                unsigned int r = ~(unsigned int)kk;
                unsigned int flat = (unsigned int)(c0 * R_N) + r;
                int p = atomicAdd(&g_count, 1);
                g_pool[p] = (kk & 0xffffffff00000000ULL) | (unsigned int)(~flat);
                g_pbox[flat] = make_float4(u.b.sx1[i], u.b.sy1[i], u.b.sx2[i], u.b.sy2[i]);
            }
        }
    }

    // ---------- ticket: last block to finish B runs phase C ----------
    __syncthreads();
    __threadfence();
    if (tid == 0) {
        int t = atomicAdd(&g_c2, 1);
        s_doC = (t == GRID - 1);
    }
    __syncthreads();
    if (!s_doC) return;
    __threadfence();

    // ---------- Phase C: shared-hist threshold + rank placement ----------
    int K = *(volatile int*)&g_count;
    int count = 0;

    if (K <= TOPK) {
        for (int i = tid; i < K; i += BLOCK) u.c.sel[i] = __ldcg(&g_pool[i]);
        count = K;
        __syncthreads();
    } else {
        bool smallK = (K <= SELCAP);
        if (smallK) for (int i = tid; i < K; i += BLOCK) u.c.cand[i] = __ldcg(&g_pool[i]);
        #pragma unroll
        for (int q = 0; q < SELCAP / BLOCK; q++) u.c.hist[tid + q * BLOCK] = 0;
        __syncthreads();
        for (int i = tid; i < K; i += BLOCK) {
            unsigned long long k = smallK ? u.c.cand[i] : __ldcg(&g_pool[i]);
            atomicAdd(&u.c.hist[kbin(k)], 1);
        }
        __syncthreads();
        // 3-barrier warp-shfl suffix scan over 2048 bins (4 bins/thread)
        int base = tid * 4;
        int h0 = u.c.hist[base], h1 = u.c.hist[base + 1];
        int h2 = u.c.hist[base + 2], h3 = u.c.hist[base + 3];
        int cs = h0 + h1 + h2 + h3;
        int v = cs;
        #pragma unroll
        for (int off = 1; off < 32; off <<= 1) {
            int nv = __shfl_down_sync(0xffffffffu, v, off);
            if (lane + off < 32) v += nv;
        }
        if (lane == 0) wtot[wid] = v;
        __syncthreads();
        if (wid == 0) {
            int w = (lane < 16) ? wtot[lane] : 0;
            #pragma unroll
            for (int off = 1; off < 16; off <<= 1) {
                int nw = __shfl_down_sync(0xffffffffu, w, off);
                if (lane + off < 16) w += nw;
            }
            if (lane < 16) wtot[lane] = w;   // suffix over warps lane..15
        }
        __syncthreads();
        int S = v + ((wid < 15) ? wtot[wid + 1] : 0);   // keys with bin >= base
        int cum = S - cs;                                // keys with bin > base+3
        int hh[4] = {h0, h1, h2, h3};
        #pragma unroll
        for (int b = 3; b >= 0; b--) {
            int h = hh[b];
            if (cum < TOPK && cum + h >= TOPK) { s_thr = base + b; s_tot = cum + h; }
            cum += h;
        }
        __syncthreads();
        int thr = s_thr;
        if (s_tot <= CANDMAX) {
            if (tid == 0) s_cnt = 0;
            __syncthreads();
            for (int i = tid; i < K; i += BLOCK) {
                unsigned long long k = smallK ? u.c.cand[i] : __ldcg(&g_pool[i]);
                if (kbin(k) >= thr) u.c.sel[atomicAdd(&s_cnt, 1)] = k;
            }
            __syncthreads();
            count = s_cnt;
        } else {
            // pathological ties: adaptive 64-bit radix descent on g_pool
            unsigned long long prefix = 0;
            int shift = 56, needed = TOPK;
            for (;;) {
                for (int i = tid; i < 256; i += BLOCK) u.c.hist[i] = 0;
                __syncthreads();
                for (int i = tid; i < K; i += BLOCK) {
                    unsigned long long k = __ldcg(&g_pool[i]);
                    bool act = (shift == 56) || ((k >> (shift + 8)) == prefix);
                    if (act) atomicAdd(&u.c.hist[(int)((k >> shift) & 255)], 1);
                }
                __syncthreads();
                if (tid == 0) {
                    int cum2 = 0, d;
                    for (d = 255; d > 0; d--) {
                        int h = u.c.hist[d];
                        if (cum2 + h >= needed) break;
                        cum2 += h;
                    }
                    s_d = d; s_cum = cum2; s_bin = u.c.hist[d];
                }
                __syncthreads();
                needed -= s_cum;
                prefix = (prefix << 8) | (unsigned int)s_d;
                int binCount = s_bin;
                shift -= 8;
                if ((TOPK - needed) + binCount <= CANDMAX || shift < 0) break;
                __syncthreads();
            }
            if (tid == 0) s_cnt = 0;
            __syncthreads();
            int sh = shift + 8;
            for (int i = tid; i < K; i += BLOCK) {
                unsigned long long k = __ldcg(&g_pool[i]);
                if ((k >> sh) >= prefix) {
                    int p = atomicAdd(&s_cnt, 1);
                    if (p < CANDMAX) u.c.sel[p] = k;
                }
            }
            __syncthreads();
            count = min(s_cnt, CANDMAX);
        }
    }

    // rank placement (keys unique -> exact ranks)
    for (int i = tid; i < count; i += BLOCK) {
        unsigned long long kk = u.c.sel[i];
        int rank = 0;
        for (int j = 0; j < count; j++) rank += (u.c.sel[j] > kk);
        if (rank < TOPK) {
            unsigned int flat = ~(unsigned int)(kk & 0xffffffffu);
            float score = unord32((unsigned int)(kk >> 32));
            int cc = flat / R_N;
            float4 b = g_pbox[flat];
            out[rank] = score;
            out[TOPK + 4 * rank + 0] = b.x;
            out[TOPK + 4 * rank + 1] = b.y;
            out[TOPK + 4 * rank + 2] = b.z;
            out[TOPK + 4 * rank + 3] = b.w;
            out[5 * TOPK + rank] = (float)(cc + 1);
        }
    }
    __syncthreads();
    if (count < TOPK && tid == 0) {
        // K < 100: fill remaining slots NEG-score, ascending unused flat idx
        int p = count;
        for (int f = 0; p < TOPK; f++) {
            bool used = false;
            for (int q = 0; q < count; q++) {
                unsigned int fl = ~(unsigned int)(u.c.sel[q] & 0xffffffffu);
                if ((int)fl == f) { used = true; break; }
            }
            if (!used) {
                int cc = f / R_N;
                int r = f - cc * R_N;
                float4 b = decode_box(props4, reg4, r, cc + 1, W, H);
                out[p] = NEGV;
                out[TOPK + 4 * p + 0] = b.x;
                out[TOPK + 4 * p + 1] = b.y;
                out[TOPK + 4 * p + 2] = b.z;
                out[TOPK + 4 * p + 3] = b.w;
                out[5 * TOPK + p] = (float)(cc + 1);
                p++;
            }
        }
    }

    // reset for next graph replay (only this block alive)
    __syncthreads();
    if (tid < NC) g_cnt[tid] = 0;
    if (tid == 0) { g_c1 = 0; g_c2 = 0; g_count = 0; }
    __threadfence();
}

// ---------------- launch ----------------
extern "C" void kernel_launch(void* const* d_in, const int* in_sizes, int n_in,
                              void* d_out, int out_size) {
    const float *logits = nullptr, *reg = nullptr, *props = nullptr;
    const void *pw = nullptr, *ph = nullptr;
    for (int i = 0; i < n_in; i++) {
        int s = in_sizes[i];
        if (s == R_N * C_N)            logits = (const float*)d_in[i];
        else if (s == R_N * C_N * 4)   reg    = (const float*)d_in[i];
        else if (s == R_N * 4)         props  = (const float*)d_in[i];
        else if (s == 1) { if (!pw) pw = d_in[i]; else ph = d_in[i]; }
    }
    k_fused<<<GRID, BLOCK>>>(logits, reg, props, pw, ph, (float*)d_out);
}